// round 13
// baseline (speedup 1.0000x reference)
#include <cuda_runtime.h>
#include <math.h>

#define NN 110
#define ALPHA 0.2f

typedef unsigned long long u64;

__device__ __forceinline__ u64 ffma2(u64 a, u64 b, u64 c) {
    u64 d; asm("fma.rn.f32x2 %0, %1, %2, %3;" : "=l"(d) : "l"(a), "l"(b), "l"(c)); return d;
}
__device__ __forceinline__ u64 splat2(float x) {
    u64 d; asm("mov.b64 %0, {%1, %1};" : "=l"(d) : "f"(x)); return d;
}
__device__ __forceinline__ float2 unpack2(u64 v) {
    float2 r; asm("mov.b64 {%0, %1}, %2;" : "=f"(r.x), "=f"(r.y) : "l"(v)); return r;
}
__device__ __forceinline__ float lrelu(float v) { return v > 0.f ? v : ALPHA * v; }
__device__ __forceinline__ float sigm(float v) { return 1.f / (1.f + __expf(-v)); }
__device__ __forceinline__ float warp_sum(float v) {
#pragma unroll
    for (int o = 16; o > 0; o >>= 1) v += __shfl_xor_sync(0xffffffffu, v, o);
    return v;
}
__device__ __forceinline__ float warp_max(float v) {
#pragma unroll
    for (int o = 16; o > 0; o >>= 1) v = fmaxf(v, __shfl_xor_sync(0xffffffffu, v, o));
    return v;
}

// ---- global scratch ----
#define BMAX 2048
__device__ float    g_sigM[12100];                 // sigmoid(M), batch-invariant
__device__ float    g_h1T[(size_t)BMAX * 13200];   // [b][k=h*24+f][n]
__device__ unsigned g_am[BMAX * 440];              // [b][n][4]

// k_layer1 dynamic smem layout (floats): buf 12210 | ess 112 | ens 112 | ams 440
#define L1_BUF   0
#define L1_ESS   12210
#define L1_ENS   12322
#define L1_AMS   12434
#define L1_FLOATS (L1_AMS + 440)
#define L1_BYTES (L1_FLOATS * 4)

// ================= K0: sigmoid(M) once =================
__global__ __launch_bounds__(256)
void k_sigm(const float* __restrict__ M)
{
    int idx = blockIdx.x * 256 + threadIdx.x;
    if (idx < 12100) g_sigM[idx] = sigm(M[idx]);
}

// ====== K1 (fused): Xm stage + masks + feats GEMM + logits + sparse attn, CTA per (b,h) ======
__global__ __launch_bounds__(128)
void k_layer1(const float* __restrict__ X, const float* __restrict__ A,
              const float* __restrict__ W1, const float* __restrict__ as1,
              const float* __restrict__ an1, const float* __restrict__ b1)
{
    extern __shared__ __align__(16) float smem[];
    float* buf = smem + L1_BUF;      // Xm tile [n][111] in stage A; fs [n][26] in stage B
    float* ess = smem + L1_ESS;
    float* ens = smem + L1_ENS;
    unsigned* ams = (unsigned*)(smem + L1_AMS);
    const int b = blockIdx.x, h = blockIdx.y, tid = threadIdx.x;
    const int lane = tid & 31, wid = tid >> 5;

    const float* Xb = X + (size_t)b * 12100;
    const float* Ab = A + (size_t)b * 12100;

    // --- stage 0: build Xm tile in smem + adjacency masks ---
    for (int idx = tid; idx < 12100; idx += 128) {
        int n = idx / NN, i = idx - n * NN;
        buf[n * 111 + i] = Xb[idx] * g_sigM[idx];     // coalesced LDG; conflict-free STS
    }
    for (int w = wid; w < 440; w += 4) {
        int n = w >> 2, seg = w & 3;
        int m = seg * 32 + lane;
        float a = (m < NN) ? Ab[n * NN + m] : 0.f;
        unsigned bal = __ballot_sync(0xffffffffu, a > 0.f);
        if (lane == 0) {
            ams[w] = bal;
            if (h == 0) g_am[b * 440 + w] = bal;      // publish for k_layer2
        }
    }
    __syncthreads();

    // --- stage A: feats GEMM from smem Xm; W1 warp-uniform LDG; acc in regs ---
    u64 acc[12];
    float esv = 0.f, env = 0.f;
    if (tid < NN) {
        const float* xr = buf + tid * 111;            // row n; stride 111 -> conflict-free
        const float* wb = W1 + h * 2640;              // uniform across warp, L1-resident
#pragma unroll
        for (int j = 0; j < 12; j++) acc[j] = 0ull;
#pragma unroll 5
        for (int i = 0; i < NN; i++) {
            u64 s = splat2(xr[i]);
            const ulonglong2* w = (const ulonglong2*)(wb + i * 24);
            ulonglong2 w0 = w[0], w1_ = w[1], w2 = w[2], w3 = w[3], w4 = w[4], w5 = w[5];
            acc[0]  = ffma2(s, w0.x,  acc[0]);  acc[1]  = ffma2(s, w0.y,  acc[1]);
            acc[2]  = ffma2(s, w1_.x, acc[2]);  acc[3]  = ffma2(s, w1_.y, acc[3]);
            acc[4]  = ffma2(s, w2.x,  acc[4]);  acc[5]  = ffma2(s, w2.y,  acc[5]);
            acc[6]  = ffma2(s, w3.x,  acc[6]);  acc[7]  = ffma2(s, w3.y,  acc[7]);
            acc[8]  = ffma2(s, w4.x,  acc[8]);  acc[9]  = ffma2(s, w4.y,  acc[9]);
            acc[10] = ffma2(s, w5.x,  acc[10]); acc[11] = ffma2(s, w5.y,  acc[11]);
        }
        const u64* ap = (const u64*)(as1 + h * 24);
        const u64* np = (const u64*)(an1 + h * 24);
        u64 sa = 0ull, sb = 0ull;
#pragma unroll
        for (int j = 0; j < 12; j++) {
            sa = ffma2(acc[j], ap[j], sa);
            sb = ffma2(acc[j], np[j], sb);
        }
        float2 fa = unpack2(sa), fb = unpack2(sb);
        esv = fa.x + fa.y;
        env = fb.x + fb.y;
    }
    __syncthreads();                                  // all Xm reads done; buf reusable
    if (tid < NN) {
        u64* fr = (u64*)(buf + tid * 26);             // fs rows of 26 (26*tid even -> 8B aligned)
#pragma unroll
        for (int j = 0; j < 12; j++) fr[j] = acc[j];
        ess[tid] = esv;
        ens[tid] = env;
    }
    __syncthreads();

    // --- stage B: sparse softmax + aggregation (proven inner loop) ---
    if (tid < NN) {
        const int n = tid;
        const float es = ess[n];
        u64 agg[12];
#pragma unroll
        for (int j = 0; j < 12; j++) agg[j] = 0ull;
        float sum = 0.f;
#pragma unroll
        for (int k = 0; k < 4; k++) {
            unsigned mw = ams[n * 4 + k];
            while (mw) {
                const int m2 = __ffs(mw) - 1;
                mw &= (mw - 1);
                const int m = k * 32 + m2;
                float v = es + ens[m];
                v = v > 0.f ? v : ALPHA * v;
                const float e = __expf(v);
                sum += e;
                const u64 s = splat2(e);
                const u64* w = (const u64*)(buf + m * 26);
#pragma unroll
                for (int j = 0; j < 12; j++) agg[j] = ffma2(s, w[j], agg[j]);
            }
        }
        const float rinv = 1.f / sum;                 // self-loop => sum > 0
        float* dst = g_h1T + (size_t)b * 13200 + (h * 24) * NN + n;
#pragma unroll
        for (int j = 0; j < 12; j++) {
            float2 p = unpack2(agg[j]);
            dst[(2 * j) * NN]     = lrelu(fmaf(p.x, rinv, b1[2 * j]));   // b1 shared across heads
            dst[(2 * j + 1) * NN] = lrelu(fmaf(p.y, rinv, b1[2 * j + 1]));
        }
    }
}

// ====== K2 (fused): layer-2 projection + attention + node probs + MIL, CTA per b ======
__global__ __launch_bounds__(128, 6)
void k_layer2(const float* __restrict__ W2, const float* __restrict__ as2,
              const float* __restrict__ an2, const float* __restrict__ b2,
              const float* __restrict__ fc1, const float* __restrict__ fc2,
              float* __restrict__ out)
{
    __shared__ float w2s[1080];
    __shared__ float a2s[9], n2s[9];
    __shared__ __align__(16) float f2sl[1320];
    __shared__ float ess2[336], ens2[336];
    __shared__ unsigned ams[440];
    __shared__ float tss[112], uss[112];
    const int b = blockIdx.x, tid = threadIdx.x, lane = tid & 31, wid = tid >> 5;

    for (int idx = tid; idx < 1080; idx += 128) w2s[idx] = W2[idx];
    if (tid < 9) { a2s[tid] = as2[tid]; n2s[tid] = an2[tid]; }
    for (int idx = tid; idx < 440; idx += 128) ams[idx] = g_am[b * 440 + idx];
    __syncthreads();

    if (tid < NN) {
        float acc[9];
#pragma unroll
        for (int j = 0; j < 9; j++) acc[j] = 0.f;
        const float* xp = g_h1T + (size_t)b * 13200 + tid;
#pragma unroll 8
        for (int k = 0; k < 120; k++) {
            float xv = xp[k * NN];
#pragma unroll
            for (int h2 = 0; h2 < 3; h2++) {
#pragma unroll
                for (int f2 = 0; f2 < 3; f2++)
                    acc[h2 * 3 + f2] = fmaf(xv, w2s[h2 * 360 + k * 3 + f2], acc[h2 * 3 + f2]);
            }
        }
#pragma unroll
        for (int h2 = 0; h2 < 3; h2++) {
            float e_s = 0.f, e_n = 0.f;
#pragma unroll
            for (int f2 = 0; f2 < 3; f2++) {
                e_s = fmaf(acc[h2 * 3 + f2], a2s[h2 * 3 + f2], e_s);
                e_n = fmaf(acc[h2 * 3 + f2], n2s[h2 * 3 + f2], e_n);
            }
            ess2[h2 * 112 + tid] = e_s;
            ens2[h2 * 112 + tid] = e_n;
            float4 o; o.x = acc[h2 * 3]; o.y = acc[h2 * 3 + 1]; o.z = acc[h2 * 3 + 2]; o.w = 0.f;
            *(float4*)(f2sl + (h2 * NN + tid) * 4) = o;
        }
    }
    __syncthreads();

    if (tid < NN) {
        const int n = tid;
        float tot0 = 0.f, tot1 = 0.f, tot2 = 0.f;
#pragma unroll
        for (int h2 = 0; h2 < 3; h2++) {
            const float es = ess2[h2 * 112 + n];
            const float* ens = ens2 + h2 * 112;
            const ulonglong2* fbw = (const ulonglong2*)(f2sl + h2 * 440);
            u64 a0 = 0ull, a1 = 0ull;
            float sum = 0.f;
#pragma unroll
            for (int k = 0; k < 4; k++) {
                unsigned mw = ams[n * 4 + k];
                while (mw) {
                    const int m2 = __ffs(mw) - 1;
                    mw &= (mw - 1);
                    const int m = k * 32 + m2;
                    float v = es + ens[m];
                    v = v > 0.f ? v : ALPHA * v;
                    const float e = __expf(v);
                    sum += e;
                    const u64 s = splat2(e);
                    ulonglong2 w = fbw[m];
                    a0 = ffma2(s, w.x, a0);
                    a1 = ffma2(s, w.y, a1);
                }
            }
            const float rinv = 1.f / sum;
            float2 v0 = unpack2(a0), v1 = unpack2(a1);
            tot0 = fmaf(v0.x, rinv, tot0);
            tot1 = fmaf(v0.y, rinv, tot1);
            tot2 = fmaf(v1.x, rinv, tot2);
        }
        float z = lrelu(fmaf(tot0, (1.f / 3.f), b2[0])) * fc1[0]
                + lrelu(fmaf(tot1, (1.f / 3.f), b2[1])) * fc1[1]
                + lrelu(fmaf(tot2, (1.f / 3.f), b2[2])) * fc1[2];
        tss[tid] = sigm(z);
    }
    __syncthreads();

    if (tid < NN) {
        const int m = tid;
        float s = 0.f;
#pragma unroll 4
        for (int n2 = 0; n2 < NN; n2++) s = fmaf(tss[n2], fc2[n2 * NN + m], s);
        uss[m] = s;
    }
    __syncthreads();
    if (wid == 0) {
        float vmax = -3.4e38f;
        for (int m = lane; m < NN; m += 32) vmax = fmaxf(vmax, uss[m]);
        vmax = warp_max(vmax);
        float num = 0.f, den = 0.f;
        for (int m = lane; m < NN; m += 32) {
            float e = __expf(uss[m] - vmax);
            num = fmaf(tss[m], e, num);
            den += e;
        }
        num = warp_sum(num);
        den = warp_sum(den);
        if (lane == 0) out[b] = num / den;
    }
}

extern "C" void kernel_launch(void* const* d_in, const int* in_sizes, int n_in,
                              void* d_out, int out_size)
{
    const float* X   = (const float*)d_in[0];
    const float* A   = (const float*)d_in[1];
    const float* M   = (const float*)d_in[2];
    const float* W1  = (const float*)d_in[3];
    const float* as1 = (const float*)d_in[4];
    const float* an1 = (const float*)d_in[5];
    const float* b1  = (const float*)d_in[6];
    const float* W2  = (const float*)d_in[7];
    const float* as2 = (const float*)d_in[8];
    const float* an2 = (const float*)d_in[9];
    const float* b2  = (const float*)d_in[10];
    const float* fc1 = (const float*)d_in[11];
    const float* fc2 = (const float*)d_in[12];
    float* out = (float*)d_out;

    const int B = in_sizes[0] / (NN * NN);

    cudaFuncSetAttribute(k_layer1, cudaFuncAttributeMaxDynamicSharedMemorySize, L1_BYTES);
    k_sigm<<<48, 256>>>(M);
    k_layer1<<<dim3(B, 5), 128, L1_BYTES>>>(X, A, W1, as1, an1, b1);
    k_layer2<<<B, 128>>>(W2, as2, an2, b2, fc1, fc2, out);
}

// round 14
// speedup vs baseline: 3.4128x; 3.4128x over previous
#include <cuda_runtime.h>
#include <math.h>

#define NN 110
#define ALPHA 0.2f

typedef unsigned long long u64;

__device__ __forceinline__ u64 ffma2(u64 a, u64 b, u64 c) {
    u64 d; asm("fma.rn.f32x2 %0, %1, %2, %3;" : "=l"(d) : "l"(a), "l"(b), "l"(c)); return d;
}
__device__ __forceinline__ u64 splat2(float x) {
    u64 d; asm("mov.b64 %0, {%1, %1};" : "=l"(d) : "f"(x)); return d;
}
__device__ __forceinline__ float2 unpack2(u64 v) {
    float2 r; asm("mov.b64 {%0, %1}, %2;" : "=f"(r.x), "=f"(r.y) : "l"(v)); return r;
}
__device__ __forceinline__ float lrelu(float v) { return v > 0.f ? v : ALPHA * v; }
__device__ __forceinline__ float sigm(float v) { return 1.f / (1.f + __expf(-v)); }
__device__ __forceinline__ float warp_sum(float v) {
#pragma unroll
    for (int o = 16; o > 0; o >>= 1) v += __shfl_xor_sync(0xffffffffu, v, o);
    return v;
}
__device__ __forceinline__ float warp_max(float v) {
#pragma unroll
    for (int o = 16; o > 0; o >>= 1) v = fmaxf(v, __shfl_xor_sync(0xffffffffu, v, o));
    return v;
}

// ---- global scratch ----
#define BMAX 2048
__device__ float    g_sigM[12100];                 // sigmoid(M), batch-invariant
__device__ float    g_xmT[(size_t)BMAX * 12100];   // [b][i][n]
__device__ float    g_h1T[(size_t)BMAX * 13200];   // [b][k=h*24+f][n]
__device__ unsigned g_am[BMAX * 440];              // [b][n][4]

// ================= K0: sigmoid(M) once =================
__global__ __launch_bounds__(256)
void k_sigm(const float* __restrict__ M)
{
    int idx = blockIdx.x * 256 + threadIdx.x;
    if (idx < 12100) g_sigM[idx] = sigm(M[idx]);
}

// ================= K1: Xm transpose + adjacency masks (vectorized, 512 thr) =================
__global__ __launch_bounds__(512)
void k_prep(const float* __restrict__ X, const float* __restrict__ A)
{
    __shared__ __align__(16) float tile[110 * 111];   // 48840 B < 48 KB static cap
    const int b = blockIdx.x, tid = threadIdx.x, lane = tid & 31, wid = tid >> 5;
    const float* Xb = X + (size_t)b * 12100;
    const float* Ab = A + (size_t)b * 12100;

    // vectorized masked-input transpose into smem: 3025 float4s
    {
        const float4* x4 = (const float4*)Xb;
        const float4* m4 = (const float4*)g_sigM;
        for (int q = tid; q < 3025; q += 512) {
            float4 xv = x4[q];
            float4 mv = m4[q];
            int idx = q * 4;
            int n = idx / NN, i = idx - n * NN;
            // elements are consecutive in i (may wrap row once)
            float vals[4] = { xv.x * mv.x, xv.y * mv.y, xv.z * mv.z, xv.w * mv.w };
#pragma unroll
            for (int j = 0; j < 4; j++) {
                tile[i * 111 + n] = vals[j];
                if (++i == NN) { i = 0; n++; }
            }
        }
    }
    // adjacency bitmask (16 warps, 27-28 iters each)
    for (int w = wid; w < 440; w += 16) {
        int n = w >> 2, seg = w & 3;
        int m = seg * 32 + lane;
        float a = (m < NN) ? Ab[n * NN + m] : 0.f;
        unsigned bal = __ballot_sync(0xffffffffu, a > 0.f);
        if (lane == 0) g_am[b * 440 + w] = bal;
    }
    __syncthreads();
    // vectorized write-out of transposed tile
    {
        float4* d4 = (float4*)(g_xmT + (size_t)b * 12100);
        for (int q = tid; q < 3025; q += 512) {
            int idx = q * 4;
            int i = idx / NN, n = idx - i * NN;
            float4 o;
            float vals[4];
#pragma unroll
            for (int j = 0; j < 4; j++) {
                vals[j] = tile[i * 111 + n];
                if (++n == NN) { n = 0; i++; }
            }
            o.x = vals[0]; o.y = vals[1]; o.z = vals[2]; o.w = vals[3];
            d4[q] = o;
        }
    }
}

// ====== K2 (fused): feats GEMM + logits + sparse softmax-aggregation, CTA per (h,b) ======
// grid = (5, B): the 5 same-b CTAs are schedule-adjacent -> g_xmT slab L2-reused
__global__ __launch_bounds__(128, 5)
void k_layer1(const float* __restrict__ W1, const float* __restrict__ as1,
              const float* __restrict__ an1, const float* __restrict__ b1)
{
    __shared__ __align__(16) float w1s[2640];
    __shared__ __align__(16) float fs[110 * 26 + 4];
    __shared__ float ess[112], ens[112];
    __shared__ unsigned ams[440];
    const int h = blockIdx.x, b = blockIdx.y, tid = threadIdx.x;

    const float* wsrc = W1 + h * 2640;
    for (int idx = tid; idx < 2640; idx += 128) w1s[idx] = wsrc[idx];
    for (int idx = tid; idx < 440; idx += 128) ams[idx] = g_am[b * 440 + idx];
    __syncthreads();

    // --- stage A: feats column-thread GEMM (R11 verbatim) ---
    if (tid < NN) {
        const int n = tid;
        const float* xp = g_xmT + (size_t)b * 12100 + n;
        u64 acc[12];
#pragma unroll
        for (int j = 0; j < 12; j++) acc[j] = 0ull;
#pragma unroll 5
        for (int i = 0; i < NN; i++) {
            u64 s = splat2(xp[i * NN]);
            const ulonglong2* w = (const ulonglong2*)(w1s + i * 24);
            ulonglong2 w0 = w[0], w1_ = w[1], w2 = w[2], w3 = w[3], w4 = w[4], w5 = w[5];
            acc[0]  = ffma2(s, w0.x,  acc[0]);  acc[1]  = ffma2(s, w0.y,  acc[1]);
            acc[2]  = ffma2(s, w1_.x, acc[2]);  acc[3]  = ffma2(s, w1_.y, acc[3]);
            acc[4]  = ffma2(s, w2.x,  acc[4]);  acc[5]  = ffma2(s, w2.y,  acc[5]);
            acc[6]  = ffma2(s, w3.x,  acc[6]);  acc[7]  = ffma2(s, w3.y,  acc[7]);
            acc[8]  = ffma2(s, w4.x,  acc[8]);  acc[9]  = ffma2(s, w4.y,  acc[9]);
            acc[10] = ffma2(s, w5.x,  acc[10]); acc[11] = ffma2(s, w5.y,  acc[11]);
        }
        u64* fr = (u64*)(fs + n * 26);
#pragma unroll
        for (int j = 0; j < 12; j++) fr[j] = acc[j];
        const u64* ap = (const u64*)(as1 + h * 24);
        const u64* np = (const u64*)(an1 + h * 24);
        u64 sa = 0ull, sb = 0ull;
#pragma unroll
        for (int j = 0; j < 12; j++) {
            sa = ffma2(acc[j], ap[j], sa);
            sb = ffma2(acc[j], np[j], sb);
        }
        float2 fa = unpack2(sa), fb = unpack2(sb);
        ess[n] = fa.x + fa.y;
        ens[n] = fb.x + fb.y;
    }
    __syncthreads();

    // --- stage B: sparse softmax + aggregation (R11 verbatim) ---
    if (tid < NN) {
        const int n = tid;
        const float es = ess[n];
        u64 acc[12];
#pragma unroll
        for (int j = 0; j < 12; j++) acc[j] = 0ull;
        float sum = 0.f;
#pragma unroll
        for (int k = 0; k < 4; k++) {
            unsigned mw = ams[n * 4 + k];
            while (mw) {
                const int m2 = __ffs(mw) - 1;
                mw &= (mw - 1);
                const int m = k * 32 + m2;
                float v = es + ens[m];
                v = v > 0.f ? v : ALPHA * v;
                const float e = __expf(v);
                sum += e;
                const u64 s = splat2(e);
                const u64* w = (const u64*)(fs + m * 26);
#pragma unroll
                for (int j = 0; j < 12; j++) acc[j] = ffma2(s, w[j], acc[j]);
            }
        }
        const float rinv = 1.f / sum;          // self-loop => sum > 0
        float* dst = g_h1T + (size_t)b * 13200 + (h * 24) * NN + n;
#pragma unroll
        for (int j = 0; j < 12; j++) {
            float2 p = unpack2(acc[j]);
            dst[(2 * j) * NN]     = lrelu(fmaf(p.x, rinv, b1[2 * j]));     // b1 shared across heads
            dst[(2 * j + 1) * NN] = lrelu(fmaf(p.y, rinv, b1[2 * j + 1]));
        }
    }
}

// ====== K3 (fused): layer-2 projection + attention + node probs + MIL, CTA per b ======
__global__ __launch_bounds__(128, 6)
void k_layer2(const float* __restrict__ W2, const float* __restrict__ as2,
              const float* __restrict__ an2, const float* __restrict__ b2,
              const float* __restrict__ fc1, const float* __restrict__ fc2,
              float* __restrict__ out)
{
    __shared__ float w2s[1080];
    __shared__ float a2s[9], n2s[9];
    __shared__ __align__(16) float f2sl[1320];
    __shared__ float ess2[336], ens2[336];
    __shared__ unsigned ams[440];
    __shared__ float tss[112], uss[112];
    const int b = blockIdx.x, tid = threadIdx.x, lane = tid & 31, wid = tid >> 5;

    for (int idx = tid; idx < 1080; idx += 128) w2s[idx] = W2[idx];
    if (tid < 9) { a2s[tid] = as2[tid]; n2s[tid] = an2[tid]; }
    for (int idx = tid; idx < 440; idx += 128) ams[idx] = g_am[b * 440 + idx];
    __syncthreads();

    if (tid < NN) {
        float acc[9];
#pragma unroll
        for (int j = 0; j < 9; j++) acc[j] = 0.f;
        const float* xp = g_h1T + (size_t)b * 13200 + tid;
#pragma unroll 8
        for (int k = 0; k < 120; k++) {
            float xv = xp[k * NN];
#pragma unroll
            for (int h2 = 0; h2 < 3; h2++) {
#pragma unroll
                for (int f2 = 0; f2 < 3; f2++)
                    acc[h2 * 3 + f2] = fmaf(xv, w2s[h2 * 360 + k * 3 + f2], acc[h2 * 3 + f2]);
            }
        }
#pragma unroll
        for (int h2 = 0; h2 < 3; h2++) {
            float e_s = 0.f, e_n = 0.f;
#pragma unroll
            for (int f2 = 0; f2 < 3; f2++) {
                e_s = fmaf(acc[h2 * 3 + f2], a2s[h2 * 3 + f2], e_s);
                e_n = fmaf(acc[h2 * 3 + f2], n2s[h2 * 3 + f2], e_n);
            }
            ess2[h2 * 112 + tid] = e_s;
            ens2[h2 * 112 + tid] = e_n;
            float4 o; o.x = acc[h2 * 3]; o.y = acc[h2 * 3 + 1]; o.z = acc[h2 * 3 + 2]; o.w = 0.f;
            *(float4*)(f2sl + (h2 * NN + tid) * 4) = o;
        }
    }
    __syncthreads();

    if (tid < NN) {
        const int n = tid;
        float tot0 = 0.f, tot1 = 0.f, tot2 = 0.f;
#pragma unroll
        for (int h2 = 0; h2 < 3; h2++) {
            const float es = ess2[h2 * 112 + n];
            const float* ens = ens2 + h2 * 112;
            const ulonglong2* fbw = (const ulonglong2*)(f2sl + h2 * 440);
            u64 a0 = 0ull, a1 = 0ull;
            float sum = 0.f;
#pragma unroll
            for (int k = 0; k < 4; k++) {
                unsigned mw = ams[n * 4 + k];
                while (mw) {
                    const int m2 = __ffs(mw) - 1;
                    mw &= (mw - 1);
                    const int m = k * 32 + m2;
                    float v = es + ens[m];
                    v = v > 0.f ? v : ALPHA * v;
                    const float e = __expf(v);
                    sum += e;
                    const u64 s = splat2(e);
                    ulonglong2 w = fbw[m];
                    a0 = ffma2(s, w.x, a0);
                    a1 = ffma2(s, w.y, a1);
                }
            }
            const float rinv = 1.f / sum;
            float2 v0 = unpack2(a0), v1 = unpack2(a1);
            tot0 = fmaf(v0.x, rinv, tot0);
            tot1 = fmaf(v0.y, rinv, tot1);
            tot2 = fmaf(v1.x, rinv, tot2);
        }
        float z = lrelu(fmaf(tot0, (1.f / 3.f), b2[0])) * fc1[0]
                + lrelu(fmaf(tot1, (1.f / 3.f), b2[1])) * fc1[1]
                + lrelu(fmaf(tot2, (1.f / 3.f), b2[2])) * fc1[2];
        tss[tid] = sigm(z);
    }
    __syncthreads();

    if (tid < NN) {
        const int m = tid;
        float s = 0.f;
#pragma unroll 4
        for (int n2 = 0; n2 < NN; n2++) s = fmaf(tss[n2], fc2[n2 * NN + m], s);
        uss[m] = s;
    }
    __syncthreads();
    if (wid == 0) {
        float vmax = -3.4e38f;
        for (int m = lane; m < NN; m += 32) vmax = fmaxf(vmax, uss[m]);
        vmax = warp_max(vmax);
        float num = 0.f, den = 0.f;
        for (int m = lane; m < NN; m += 32) {
            float e = __expf(uss[m] - vmax);
            num = fmaf(tss[m], e, num);
            den += e;
        }
        num = warp_sum(num);
        den = warp_sum(den);
        if (lane == 0) out[b] = num / den;
    }
}

extern "C" void kernel_launch(void* const* d_in, const int* in_sizes, int n_in,
                              void* d_out, int out_size)
{
    const float* X   = (const float*)d_in[0];
    const float* A   = (const float*)d_in[1];
    const float* M   = (const float*)d_in[2];
    const float* W1  = (const float*)d_in[3];
    const float* as1 = (const float*)d_in[4];
    const float* an1 = (const float*)d_in[5];
    const float* b1  = (const float*)d_in[6];
    const float* W2  = (const float*)d_in[7];
    const float* as2 = (const float*)d_in[8];
    const float* an2 = (const float*)d_in[9];
    const float* b2  = (const float*)d_in[10];
    const float* fc1 = (const float*)d_in[11];
    const float* fc2 = (const float*)d_in[12];
    float* out = (float*)d_out;

    const int B = in_sizes[0] / (NN * NN);

    k_sigm<<<48, 256>>>(M);
    k_prep<<<B, 512>>>(X, A);
    k_layer1<<<dim3(5, B), 128>>>(W1, as1, an1, b1);
    k_layer2<<<B, 128>>>(W2, as2, an2, b2, fc1, fc2, out);
}

// round 15
// speedup vs baseline: 3.5293x; 1.0341x over previous
#include <cuda_runtime.h>
#include <math.h>

#define NN 110
#define ALPHA 0.2f

typedef unsigned long long u64;

__device__ __forceinline__ u64 ffma2(u64 a, u64 b, u64 c) {
    u64 d; asm("fma.rn.f32x2 %0, %1, %2, %3;" : "=l"(d) : "l"(a), "l"(b), "l"(c)); return d;
}
__device__ __forceinline__ u64 splat2(float x) {
    u64 d; asm("mov.b64 %0, {%1, %1};" : "=l"(d) : "f"(x)); return d;
}
__device__ __forceinline__ float2 unpack2(u64 v) {
    float2 r; asm("mov.b64 {%0, %1}, %2;" : "=f"(r.x), "=f"(r.y) : "l"(v)); return r;
}
__device__ __forceinline__ float lrelu(float v) { return v > 0.f ? v : ALPHA * v; }
__device__ __forceinline__ float sigm(float v) { return 1.f / (1.f + __expf(-v)); }
__device__ __forceinline__ float warp_sum(float v) {
#pragma unroll
    for (int o = 16; o > 0; o >>= 1) v += __shfl_xor_sync(0xffffffffu, v, o);
    return v;
}
__device__ __forceinline__ float warp_max(float v) {
#pragma unroll
    for (int o = 16; o > 0; o >>= 1) v = fmaxf(v, __shfl_xor_sync(0xffffffffu, v, o));
    return v;
}

// ---- global scratch ----
#define BMAX 2048
__device__ float    g_sigM[12100];                 // sigmoid(M), batch-invariant
__device__ float    g_xmT[(size_t)BMAX * 12100];   // [b][i][n]
__device__ float    g_h1T[(size_t)BMAX * 13200];   // [b][k=h*24+f][n]
__device__ unsigned g_am[BMAX * 440];              // [b][n][4]

// ================= K0: sigmoid(M) once =================
__global__ __launch_bounds__(256)
void k_sigm(const float* __restrict__ M)
{
    int idx = blockIdx.x * 256 + threadIdx.x;
    if (idx < 12100) g_sigM[idx] = sigm(M[idx]);
}

// ================= K1: Xm transpose + adjacency masks (vectorized, 512 thr) =================
__global__ __launch_bounds__(512)
void k_prep(const float* __restrict__ X, const float* __restrict__ A)
{
    __shared__ __align__(16) float tile[110 * 111];
    const int b = blockIdx.x, tid = threadIdx.x, lane = tid & 31, wid = tid >> 5;
    const float* Xb = X + (size_t)b * 12100;
    const float* Ab = A + (size_t)b * 12100;

    {
        const float4* x4 = (const float4*)Xb;
        const float4* m4 = (const float4*)g_sigM;
        for (int q = tid; q < 3025; q += 512) {
            float4 xv = x4[q];
            float4 mv = m4[q];
            int idx = q * 4;
            int n = idx / NN, i = idx - n * NN;
            float vals[4] = { xv.x * mv.x, xv.y * mv.y, xv.z * mv.z, xv.w * mv.w };
#pragma unroll
            for (int j = 0; j < 4; j++) {
                tile[i * 111 + n] = vals[j];
                if (++i == NN) { i = 0; n++; }
            }
        }
    }
    for (int w = wid; w < 440; w += 16) {
        int n = w >> 2, seg = w & 3;
        int m = seg * 32 + lane;
        float a = (m < NN) ? Ab[n * NN + m] : 0.f;
        unsigned bal = __ballot_sync(0xffffffffu, a > 0.f);
        if (lane == 0) g_am[b * 440 + w] = bal;
    }
    __syncthreads();
    {
        float4* d4 = (float4*)(g_xmT + (size_t)b * 12100);
        for (int q = tid; q < 3025; q += 512) {
            int idx = q * 4;
            int i = idx / NN, n = idx - i * NN;
            float4 o;
            float vals[4];
#pragma unroll
            for (int j = 0; j < 4; j++) {
                vals[j] = tile[i * 111 + n];
                if (++n == NN) { n = 0; i++; }
            }
            o.x = vals[0]; o.y = vals[1]; o.z = vals[2]; o.w = vals[3];
            d4[q] = o;
        }
    }
}

// ====== K2: layer-1, 256 threads, column-halved: thread (half,n) owns 12 of 24 cols ======
__global__ __launch_bounds__(256, 5)
void k_layer1(const float* __restrict__ W1, const float* __restrict__ as1,
              const float* __restrict__ an1, const float* __restrict__ b1)
{
    __shared__ __align__(16) float w1s[2640];
    __shared__ __align__(16) float fs[110 * 26 + 4];
    __shared__ float pes[220], pen[220];     // per-half logit partials
    __shared__ float ess[112], ens[112];
    __shared__ unsigned ams[440];
    const int h = blockIdx.x, b = blockIdx.y, tid = threadIdx.x;

    const float* wsrc = W1 + h * 2640;
    for (int idx = tid; idx < 2640; idx += 256) w1s[idx] = wsrc[idx];
    for (int idx = tid; idx < 440; idx += 256) ams[idx] = g_am[b * 440 + idx];
    __syncthreads();

    const int half = tid / NN;               // 0 or 1 for tid<220
    const int n = tid - half * NN;
    const int c0 = half * 12;

    // --- stage A: half-row GEMM (6 u64 accumulators) + partial logits ---
    if (tid < 220) {
        const float* xp = g_xmT + (size_t)b * 12100 + n;
        u64 acc[6];
#pragma unroll
        for (int j = 0; j < 6; j++) acc[j] = 0ull;
#pragma unroll 5
        for (int i = 0; i < NN; i++) {
            u64 s = splat2(xp[i * NN]);      // same addr for both halves -> L1 broadcast
            const u64* w = (const u64*)(w1s + i * 24 + c0);
            acc[0] = ffma2(s, w[0], acc[0]); acc[1] = ffma2(s, w[1], acc[1]);
            acc[2] = ffma2(s, w[2], acc[2]); acc[3] = ffma2(s, w[3], acc[3]);
            acc[4] = ffma2(s, w[4], acc[4]); acc[5] = ffma2(s, w[5], acc[5]);
        }
        u64* fr = (u64*)(fs + n * 26 + c0);
#pragma unroll
        for (int j = 0; j < 6; j++) fr[j] = acc[j];
        const u64* ap = (const u64*)(as1 + h * 24 + c0);
        const u64* np = (const u64*)(an1 + h * 24 + c0);
        u64 sa = 0ull, sb = 0ull;
#pragma unroll
        for (int j = 0; j < 6; j++) {
            sa = ffma2(acc[j], ap[j], sa);
            sb = ffma2(acc[j], np[j], sb);
        }
        float2 fa = unpack2(sa), fb = unpack2(sb);
        pes[tid] = fa.x + fa.y;
        pen[tid] = fb.x + fb.y;
    }
    __syncthreads();
    if (tid < NN) {
        ess[tid] = pes[tid] + pes[tid + NN];
        ens[tid] = pen[tid] + pen[tid + NN];
    }
    __syncthreads();

    // --- stage B: sparse softmax + half-aggregation ---
    if (tid < 220) {
        const float es = ess[n];
        u64 agg[6];
#pragma unroll
        for (int j = 0; j < 6; j++) agg[j] = 0ull;
        float sum = 0.f;
#pragma unroll
        for (int k = 0; k < 4; k++) {
            unsigned mw = ams[n * 4 + k];
            while (mw) {
                const int m2 = __ffs(mw) - 1;
                mw &= (mw - 1);
                const int m = k * 32 + m2;
                float v = es + ens[m];
                v = v > 0.f ? v : ALPHA * v;
                const float e = __expf(v);
                sum += e;
                const u64 s = splat2(e);
                const u64* w = (const u64*)(fs + m * 26 + c0);
                agg[0] = ffma2(s, w[0], agg[0]); agg[1] = ffma2(s, w[1], agg[1]);
                agg[2] = ffma2(s, w[2], agg[2]); agg[3] = ffma2(s, w[3], agg[3]);
                agg[4] = ffma2(s, w[4], agg[4]); agg[5] = ffma2(s, w[5], agg[5]);
            }
        }
        const float rinv = 1.f / sum;        // self-loop => sum > 0
        float* dst = g_h1T + (size_t)b * 13200 + (h * 24 + c0) * NN + n;
        const float* bb = b1 + c0;           // b1 shape [24], shared across heads
#pragma unroll
        for (int j = 0; j < 6; j++) {
            float2 p = unpack2(agg[j]);
            dst[(2 * j) * NN]     = lrelu(fmaf(p.x, rinv, bb[2 * j]));
            dst[(2 * j + 1) * NN] = lrelu(fmaf(p.y, rinv, bb[2 * j + 1]));
        }
    }
}

// ====== K3: layer-2, 384 threads, head-split: thread (h2,n) ======
__global__ __launch_bounds__(384, 4)
void k_layer2(const float* __restrict__ W2, const float* __restrict__ as2,
              const float* __restrict__ an2, const float* __restrict__ b2,
              const float* __restrict__ fc1, const float* __restrict__ fc2,
              float* __restrict__ out)
{
    __shared__ float w2s[1080];
    __shared__ float a2s[9], n2s[9];
    __shared__ __align__(16) float f2sl[1320];
    __shared__ __align__(16) float hps[1320];    // per-head scaled aggregation results
    __shared__ float ess2[336], ens2[336];
    __shared__ unsigned ams[440];
    __shared__ float tss[112], uss[112];
    const int b = blockIdx.x, tid = threadIdx.x, lane = tid & 31, wid = tid >> 5;

    for (int idx = tid; idx < 1080; idx += 384) w2s[idx] = W2[idx];
    if (tid < 9) { a2s[tid] = as2[tid]; n2s[tid] = an2[tid]; }
    for (int idx = tid; idx < 440; idx += 384) ams[idx] = g_am[b * 440 + idx];
    __syncthreads();

    const int h2 = tid / NN;                 // 0..2 for tid<330
    const int n = tid - h2 * NN;

    // --- stage A: head-split projection (3 accumulators) + logit halves ---
    if (tid < 330) {
        float a0 = 0.f, a1 = 0.f, a2v = 0.f;
        const float* xp = g_h1T + (size_t)b * 13200 + n;
        const float* wp = w2s + h2 * 360;
#pragma unroll 8
        for (int k = 0; k < 120; k++) {
            float xv = xp[k * NN];           // same addr across the 3 h2 threads -> L1 hit
            a0 = fmaf(xv, wp[k * 3 + 0], a0);
            a1 = fmaf(xv, wp[k * 3 + 1], a1);
            a2v = fmaf(xv, wp[k * 3 + 2], a2v);
        }
        float e_s = a0 * a2s[h2 * 3] + a1 * a2s[h2 * 3 + 1] + a2v * a2s[h2 * 3 + 2];
        float e_n = a0 * n2s[h2 * 3] + a1 * n2s[h2 * 3 + 1] + a2v * n2s[h2 * 3 + 2];
        ess2[h2 * 112 + n] = e_s;
        ens2[h2 * 112 + n] = e_n;
        float4 o; o.x = a0; o.y = a1; o.z = a2v; o.w = 0.f;
        *(float4*)(f2sl + (h2 * NN + n) * 4) = o;
    }
    __syncthreads();

    // --- stage B: head-split sparse attention ---
    if (tid < 330) {
        const float es = ess2[h2 * 112 + n];
        const float* ens = ens2 + h2 * 112;
        const ulonglong2* fbw = (const ulonglong2*)(f2sl + h2 * 440);
        u64 a0 = 0ull, a1 = 0ull;
        float sum = 0.f;
#pragma unroll
        for (int k = 0; k < 4; k++) {
            unsigned mw = ams[n * 4 + k];
            while (mw) {
                const int m2 = __ffs(mw) - 1;
                mw &= (mw - 1);
                const int m = k * 32 + m2;
                float v = es + ens[m];
                v = v > 0.f ? v : ALPHA * v;
                const float e = __expf(v);
                sum += e;
                const u64 s = splat2(e);
                ulonglong2 w = fbw[m];
                a0 = ffma2(s, w.x, a0);
                a1 = ffma2(s, w.y, a1);
            }
        }
        const float rinv = 1.f / sum;
        float2 v0 = unpack2(a0), v1 = unpack2(a1);
        float4 o; o.x = v0.x * rinv; o.y = v0.y * rinv; o.z = v1.x * rinv; o.w = 0.f;
        *(float4*)(hps + (h2 * NN + n) * 4) = o;
    }
    __syncthreads();

    // --- stage C: head mean -> node probs ---
    if (tid < NN) {
        float4 p0 = *(const float4*)(hps + tid * 4);
        float4 p1 = *(const float4*)(hps + (NN + tid) * 4);
        float4 p2 = *(const float4*)(hps + (2 * NN + tid) * 4);
        float z = lrelu(fmaf((p0.x + p1.x + p2.x), (1.f / 3.f), b2[0])) * fc1[0]
                + lrelu(fmaf((p0.y + p1.y + p2.y), (1.f / 3.f), b2[1])) * fc1[1]
                + lrelu(fmaf((p0.z + p1.z + p2.z), (1.f / 3.f), b2[2])) * fc1[2];
        tss[tid] = sigm(z);
    }
    __syncthreads();

    // --- stage D: MIL pooling (split-K x3 over 330 threads) ---
    if (tid < 330) {
        const int m = n;                     // reuse (h2,n) mapping: h2 = K-chunk
        float s = 0.f;
        int n0 = h2 * 37, n1 = n0 + 37 < NN ? n0 + 37 : NN;
        for (int n2 = n0; n2 < n1; n2++) s = fmaf(tss[n2], fc2[n2 * NN + m], s);
        // combine 3 partials via smem (threads m, m+110, m+220 pattern unavailable in-warp)
        if (h2 == 0) uss[m] = 0.f;
    }
    __syncthreads();
    if (tid < 330) {
        int n0 = h2 * 37, n1 = n0 + 37 < NN ? n0 + 37 : NN;
        float s = 0.f;
        for (int n2 = n0; n2 < n1; n2++) s = fmaf(tss[n2], fc2[n2 * NN + n], s);
        atomicAdd(&uss[n], s);
    }
    __syncthreads();
    if (wid == 0) {
        float vmax = -3.4e38f;
        for (int m = lane; m < NN; m += 32) vmax = fmaxf(vmax, uss[m]);
        vmax = warp_max(vmax);
        float num = 0.f, den = 0.f;
        for (int m = lane; m < NN; m += 32) {
            float e = __expf(uss[m] - vmax);
            num = fmaf(tss[m], e, num);
            den += e;
        }
        num = warp_sum(num);
        den = warp_sum(den);
        if (lane == 0) out[b] = num / den;
    }
}

extern "C" void kernel_launch(void* const* d_in, const int* in_sizes, int n_in,
                              void* d_out, int out_size)
{
    const float* X   = (const float*)d_in[0];
    const float* A   = (const float*)d_in[1];
    const float* M   = (const float*)d_in[2];
    const float* W1  = (const float*)d_in[3];
    const float* as1 = (const float*)d_in[4];
    const float* an1 = (const float*)d_in[5];
    const float* b1  = (const float*)d_in[6];
    const float* W2  = (const float*)d_in[7];
    const float* as2 = (const float*)d_in[8];
    const float* an2 = (const float*)d_in[9];
    const float* b2  = (const float*)d_in[10];
    const float* fc1 = (const float*)d_in[11];
    const float* fc2 = (const float*)d_in[12];
    float* out = (float*)d_out;

    const int B = in_sizes[0] / (NN * NN);

    k_sigm<<<48, 256>>>(M);
    k_prep<<<B, 512>>>(X, A);
    k_layer1<<<dim3(5, B), 256>>>(W1, as1, an1, b1);
    k_layer2<<<B, 384>>>(W2, as2, an2, b2, fc1, fc2, out);
}